// round 2
// baseline (speedup 1.0000x reference)
#include <cuda_runtime.h>

#define NN 50000
#define DD 128
#define EE 800000
#define EPSL 1e-5f

// ---------------- scratch (device globals; no allocation allowed) -------------
__device__ float g_deg[NN];
__device__ float g_dinv[NN];
__device__ float g_tmp[NN * DD];   // dinv[i] * (ReLU(LN(h_i)) @ W)
__device__ float g_x1[NN * DD];    // x after layer0 + residual
__device__ float g_h2[NN * DD];    // layer1 output

// ---------------- degree / dinv ----------------------------------------------
__global__ void k_deg_init() {
    int i = blockIdx.x * blockDim.x + threadIdx.x;
    if (i < NN) g_deg[i] = 1.0f;  // self loop
}

__global__ void k_deg_acc(const int* __restrict__ dst) {
    int e = blockIdx.x * blockDim.x + threadIdx.x;
    if (e < EE) atomicAdd(&g_deg[dst[e]], 1.0f);
}

__global__ void k_dinv() {
    int i = blockIdx.x * blockDim.x + threadIdx.x;
    if (i < NN) g_dinv[i] = rsqrtf(g_deg[i]);
}

// ---------------- fused LN + ReLU + GEMM + dinv prescale ----------------------
// g_tmp[i] = dinv[i] * ( ReLU( (h_i - mu)*rstd*g + bt ) @ W )
// Block: 256 threads, tile 32 rows x 128 cols.
// Static smem: A tile 32x128 (16KB) + W k-half tile 64x128 (32KB) = 48KB.
#define TR 32
#define KT 64   // k-tile (two passes over k)
__global__ void __launch_bounds__(256) k_ln_gemm(const float* __restrict__ h,
                          const float* __restrict__ g,
                          const float* __restrict__ bt,
                          const float* __restrict__ W) {
    __shared__ float Ws[KT * DD];    // 32KB: rows k0..k0+63 of W
    __shared__ float As[TR * DD];    // 16KB

    int tid = threadIdx.x;
    int lane = tid & 31;
    int w = tid >> 5;
    int row0 = blockIdx.x * TR;

    // LayerNorm + ReLU into As: each warp handles rows w, w+8, w+16, w+24
    for (int r = w; r < TR; r += 8) {
        int row = row0 + r;
        float4 v = make_float4(0.f, 0.f, 0.f, 0.f);
        if (row < NN) v = ((const float4*)(h + (size_t)row * DD))[lane];
        float s = v.x + v.y + v.z + v.w;
        #pragma unroll
        for (int o = 16; o; o >>= 1) s += __shfl_xor_sync(0xffffffffu, s, o);
        float mu = s * (1.0f / DD);
        float dx = v.x - mu, dy = v.y - mu, dz = v.z - mu, dw = v.w - mu;
        float q = dx * dx + dy * dy + dz * dz + dw * dw;
        #pragma unroll
        for (int o = 16; o; o >>= 1) q += __shfl_xor_sync(0xffffffffu, q, o);
        float rstd = rsqrtf(q * (1.0f / DD) + EPSL);
        float4 gg = ((const float4*)g)[lane];
        float4 bb = ((const float4*)bt)[lane];
        float4 o4;
        o4.x = fmaxf(fmaf(dx * rstd, gg.x, bb.x), 0.f);
        o4.y = fmaxf(fmaf(dy * rstd, gg.y, bb.y), 0.f);
        o4.z = fmaxf(fmaf(dz * rstd, gg.z, bb.z), 0.f);
        o4.w = fmaxf(fmaf(dw * rstd, gg.w, bb.w), 0.f);
        ((float4*)(As + r * DD))[lane] = o4;
    }

    // GEMM: warp w -> rows 4w..4w+3 ; lane -> cols 4*lane..4*lane+3
    float acc[4][4];
    #pragma unroll
    for (int i = 0; i < 4; i++)
        #pragma unroll
        for (int j = 0; j < 4; j++) acc[i][j] = 0.f;

    const float* a0 = As + (w * 4 + 0) * DD;
    const float* a1 = As + (w * 4 + 1) * DD;
    const float* a2 = As + (w * 4 + 2) * DD;
    const float* a3 = As + (w * 4 + 3) * DD;

    for (int k0 = 0; k0 < DD; k0 += KT) {
        __syncthreads();
        // load W[k0:k0+KT, :] into Ws
        {
            const float4* W4 = (const float4*)(W + (size_t)k0 * DD);
            float4* Ws4 = (float4*)Ws;
            #pragma unroll
            for (int i = tid; i < KT * DD / 4; i += 256) Ws4[i] = W4[i];
        }
        __syncthreads();

        #pragma unroll 8
        for (int kk = 0; kk < KT; kk++) {
            int k = k0 + kk;
            float va0 = a0[k];
            float va1 = a1[k];
            float va2 = a2[k];
            float va3 = a3[k];
            float4 wv = ((const float4*)(Ws + kk * DD))[lane];
            acc[0][0] = fmaf(va0, wv.x, acc[0][0]);
            acc[0][1] = fmaf(va0, wv.y, acc[0][1]);
            acc[0][2] = fmaf(va0, wv.z, acc[0][2]);
            acc[0][3] = fmaf(va0, wv.w, acc[0][3]);
            acc[1][0] = fmaf(va1, wv.x, acc[1][0]);
            acc[1][1] = fmaf(va1, wv.y, acc[1][1]);
            acc[1][2] = fmaf(va1, wv.z, acc[1][2]);
            acc[1][3] = fmaf(va1, wv.w, acc[1][3]);
            acc[2][0] = fmaf(va2, wv.x, acc[2][0]);
            acc[2][1] = fmaf(va2, wv.y, acc[2][1]);
            acc[2][2] = fmaf(va2, wv.z, acc[2][2]);
            acc[2][3] = fmaf(va2, wv.w, acc[2][3]);
            acc[3][0] = fmaf(va3, wv.x, acc[3][0]);
            acc[3][1] = fmaf(va3, wv.y, acc[3][1]);
            acc[3][2] = fmaf(va3, wv.z, acc[3][2]);
            acc[3][3] = fmaf(va3, wv.w, acc[3][3]);
        }
    }

    #pragma unroll
    for (int i = 0; i < 4; i++) {
        int row = row0 + w * 4 + i;
        if (row < NN) {
            float dv = g_dinv[row];
            float4 o;
            o.x = acc[i][0] * dv;
            o.y = acc[i][1] * dv;
            o.z = acc[i][2] * dv;
            o.w = acc[i][3] * dv;
            ((float4*)(g_tmp + (size_t)row * DD))[lane] = o;
        }
    }
}

// ---------------- init output: bias + self-loop + optional residual -----------
// out[i][d] = b[d] + dinv[i]*tmp[i][d] (+ res[i][d])
__global__ void k_init_out(float* __restrict__ out, const float* __restrict__ b,
                           const float* __restrict__ res) {
    int idx = blockIdx.x * blockDim.x + threadIdx.x;  // over N*D/4
    if (idx >= NN * DD / 4) return;
    int row = idx >> 5;       // DD/4 = 32
    int c4 = idx & 31;
    float dv = g_dinv[row];
    float4 t = ((const float4*)g_tmp)[idx];
    float4 bb = ((const float4*)b)[c4];
    float4 o;
    o.x = fmaf(dv, t.x, bb.x);
    o.y = fmaf(dv, t.y, bb.y);
    o.z = fmaf(dv, t.z, bb.z);
    o.w = fmaf(dv, t.w, bb.w);
    if (res) {
        float4 r = ((const float4*)res)[idx];
        o.x += r.x; o.y += r.y; o.z += r.z; o.w += r.w;
    }
    ((float4*)out)[idx] = o;
}

// ---------------- edge scatter: out[dst] += dinv[dst] * tmp[src] --------------
// one warp per edge; lane covers 4 contiguous floats -> red.global.add.v4.f32
__global__ void k_scatter(const int* __restrict__ src, const int* __restrict__ dst,
                          float* __restrict__ out) {
    int gw = (blockIdx.x * blockDim.x + threadIdx.x) >> 5;
    int lane = threadIdx.x & 31;
    if (gw >= EE) return;
    int s = src[gw];
    int t = dst[gw];
    float dv = g_dinv[t];
    float4 v = ((const float4*)(g_tmp + (size_t)s * DD))[lane];
    float* o = out + (size_t)t * DD + lane * 4;
    asm volatile("red.global.add.v4.f32 [%0], {%1,%2,%3,%4};"
                 :: "l"(o), "f"(v.x * dv), "f"(v.y * dv), "f"(v.z * dv), "f"(v.w * dv)
                 : "memory");
}

// ---------------- launch ------------------------------------------------------
extern "C" void kernel_launch(void* const* d_in, const int* in_sizes, int n_in,
                              void* d_out, int out_size) {
    const float* x   = (const float*)d_in[0];
    const int*   ei  = (const int*)d_in[1];
    const int*   src = ei;
    const int*   dst = ei + EE;
    const float* lng0 = (const float*)d_in[2];
    const float* lnb0 = (const float*)d_in[3];
    const float* W0   = (const float*)d_in[4];
    const float* b0   = (const float*)d_in[5];
    const float* lng1 = (const float*)d_in[6];
    const float* lnb1 = (const float*)d_in[7];
    const float* W1   = (const float*)d_in[8];
    const float* b1   = (const float*)d_in[9];
    const float* lng2 = (const float*)d_in[10];
    const float* lnb2 = (const float*)d_in[11];
    const float* W2   = (const float*)d_in[12];
    const float* b2   = (const float*)d_in[13];
    float* out = (float*)d_out;

    float* d_x1;  cudaGetSymbolAddress((void**)&d_x1,  g_x1);
    float* d_h2;  cudaGetSymbolAddress((void**)&d_h2,  g_h2);

    // degree + dinv
    k_deg_init<<<(NN + 255) / 256, 256>>>();
    k_deg_acc<<<(EE + 255) / 256, 256>>>(dst);
    k_dinv<<<(NN + 255) / 256, 256>>>();

    const int gemm_blocks = (NN + TR - 1) / TR;
    const int init_blocks = (NN * DD / 4 + 255) / 256;
    const int scat_blocks = (EE + 7) / 8;   // 8 warps/block, warp per edge

    // layer 0: x -> g_x1 (residual = x)
    k_ln_gemm<<<gemm_blocks, 256>>>(x, lng0, lnb0, W0);
    k_init_out<<<init_blocks, 256>>>(d_x1, b0, x);
    k_scatter<<<scat_blocks, 256>>>(src, dst, d_x1);

    // layer 1: g_x1 -> g_h2 (no residual)
    k_ln_gemm<<<gemm_blocks, 256>>>(d_x1, lng1, lnb1, W1);
    k_init_out<<<init_blocks, 256>>>(d_h2, b1, nullptr);
    k_scatter<<<scat_blocks, 256>>>(src, dst, d_h2);

    // layer 2: g_h2 -> out (residual = g_x1)
    k_ln_gemm<<<gemm_blocks, 256>>>(d_h2, lng2, lnb2, W2);
    k_init_out<<<init_blocks, 256>>>(out, b2, d_x1);
    k_scatter<<<scat_blocks, 256>>>(src, dst, out);
}

// round 3
// speedup vs baseline: 1.6057x; 1.6057x over previous
#include <cuda_runtime.h>

#define NN 50000
#define DD 128
#define EE 800000
#define EPSL 1e-5f

#define SCH 512
#define SNB ((NN + SCH - 1) / SCH)   // 98

// ---------------- scratch (device globals; no allocation allowed) -------------
__device__ float g_dinv[NN];
__device__ float g_tmp[NN * DD];   // dinv[i] * (ReLU(LN(h_i)) @ W)
__device__ float g_x1[NN * DD];    // x after layer0 + residual
__device__ float g_h2[NN * DD];    // layer1 output
__device__ int   g_cnt[NN];
__device__ int   g_start[NN];
__device__ int   g_cursor[NN];
__device__ int   g_esrc[EE];       // edge srcs bucketed by dst (CSR)
__device__ int   g_csum[SNB];

// ---------------- CSR build ----------------------------------------------------
__global__ void k_zero() {
    int i = blockIdx.x * blockDim.x + threadIdx.x;
    if (i < NN) g_cnt[i] = 0;
}

__global__ void k_hist(const int* __restrict__ dst) {
    int e = blockIdx.x * blockDim.x + threadIdx.x;
    if (e < EE) atomicAdd(&g_cnt[dst[e]], 1);
}

__global__ void k_dinv_k() {
    int i = blockIdx.x * blockDim.x + threadIdx.x;
    if (i < NN) g_dinv[i] = rsqrtf(1.0f + (float)g_cnt[i]);  // deg incl self loop
}

// per-chunk sums
__global__ void __launch_bounds__(SCH) k_scan_a() {
    __shared__ int sm[SCH];
    int t = threadIdx.x;
    int i = blockIdx.x * SCH + t;
    sm[t] = (i < NN) ? g_cnt[i] : 0;
    __syncthreads();
    for (int off = SCH / 2; off > 0; off >>= 1) {
        if (t < off) sm[t] += sm[t + off];
        __syncthreads();
    }
    if (t == 0) g_csum[blockIdx.x] = sm[0];
}

// serial exclusive scan of chunk sums (98 values)
__global__ void k_scan_b() {
    if (threadIdx.x == 0 && blockIdx.x == 0) {
        int run = 0;
        for (int j = 0; j < SNB; j++) {
            int v = g_csum[j];
            g_csum[j] = run;
            run += v;
        }
    }
}

// in-chunk exclusive scan + chunk offset -> start/cursor
__global__ void __launch_bounds__(SCH) k_scan_c() {
    __shared__ int sm[SCH];
    int t = threadIdx.x;
    int i = blockIdx.x * SCH + t;
    int v = (i < NN) ? g_cnt[i] : 0;
    sm[t] = v;
    __syncthreads();
    for (int off = 1; off < SCH; off <<= 1) {
        int x = (t >= off) ? sm[t - off] : 0;
        __syncthreads();
        sm[t] += x;
        __syncthreads();
    }
    if (i < NN) {
        int excl = sm[t] - v + g_csum[blockIdx.x];
        g_start[i] = excl;
        g_cursor[i] = excl;
    }
}

__global__ void k_bucket(const int* __restrict__ src, const int* __restrict__ dst) {
    int e = blockIdx.x * blockDim.x + threadIdx.x;
    if (e < EE) {
        int pos = atomicAdd(&g_cursor[dst[e]], 1);
        g_esrc[pos] = src[e];
    }
}

// ---------------- fused LN + ReLU + GEMM + dinv prescale ----------------------
// g_tmp[i] = dinv[i] * ( ReLU( (h_i - mu)*rstd*g + bt ) @ W )
// Block 256 threads, tile 64 rows x 128 cols, k-tile 32. 48KB static smem.
#define TR 64
#define KT 32
__global__ void __launch_bounds__(256) k_ln_gemm(const float* __restrict__ h,
                          const float* __restrict__ g,
                          const float* __restrict__ bt,
                          const float* __restrict__ W) {
    __shared__ float As[TR * DD];    // 32KB
    __shared__ float Ws[KT * DD];    // 16KB

    int tid = threadIdx.x;
    int lane = tid & 31;
    int w = tid >> 5;
    int row0 = blockIdx.x * TR;

    // LayerNorm + ReLU into As: warp w handles rows w, w+8, ..., w+56
    for (int r = w; r < TR; r += 8) {
        int row = row0 + r;
        float4 v = make_float4(0.f, 0.f, 0.f, 0.f);
        if (row < NN) v = ((const float4*)(h + (size_t)row * DD))[lane];
        float s = v.x + v.y + v.z + v.w;
        #pragma unroll
        for (int o = 16; o; o >>= 1) s += __shfl_xor_sync(0xffffffffu, s, o);
        float mu = s * (1.0f / DD);
        float dx = v.x - mu, dy = v.y - mu, dz = v.z - mu, dw = v.w - mu;
        float q = dx * dx + dy * dy + dz * dz + dw * dw;
        #pragma unroll
        for (int o = 16; o; o >>= 1) q += __shfl_xor_sync(0xffffffffu, q, o);
        float rstd = rsqrtf(q * (1.0f / DD) + EPSL);
        float4 gg = ((const float4*)g)[lane];
        float4 bb = ((const float4*)bt)[lane];
        float4 o4;
        o4.x = fmaxf(fmaf(dx * rstd, gg.x, bb.x), 0.f);
        o4.y = fmaxf(fmaf(dy * rstd, gg.y, bb.y), 0.f);
        o4.z = fmaxf(fmaf(dz * rstd, gg.z, bb.z), 0.f);
        o4.w = fmaxf(fmaf(dw * rstd, gg.w, bb.w), 0.f);
        ((float4*)(As + r * DD))[lane] = o4;
    }

    // GEMM: warp w -> rows 8w..8w+7 ; lane -> cols 4*lane..4*lane+3
    float acc[8][4];
    #pragma unroll
    for (int i = 0; i < 8; i++)
        #pragma unroll
        for (int j = 0; j < 4; j++) acc[i][j] = 0.f;

    const float* aw = As + w * 8 * DD;

    for (int k0 = 0; k0 < DD; k0 += KT) {
        __syncthreads();
        {
            const float4* W4 = (const float4*)(W + (size_t)k0 * DD);
            float4* Ws4 = (float4*)Ws;
            #pragma unroll
            for (int i = tid; i < KT * DD / 4; i += 256) Ws4[i] = W4[i];
        }
        __syncthreads();

        #pragma unroll 8
        for (int kk = 0; kk < KT; kk++) {
            float4 wv = ((const float4*)(Ws + kk * DD))[lane];
            #pragma unroll
            for (int i = 0; i < 8; i++) {
                float va = aw[i * DD + k0 + kk];
                acc[i][0] = fmaf(va, wv.x, acc[i][0]);
                acc[i][1] = fmaf(va, wv.y, acc[i][1]);
                acc[i][2] = fmaf(va, wv.z, acc[i][2]);
                acc[i][3] = fmaf(va, wv.w, acc[i][3]);
            }
        }
    }

    #pragma unroll
    for (int i = 0; i < 8; i++) {
        int row = row0 + w * 8 + i;
        if (row < NN) {
            float dv = g_dinv[row];
            float4 o;
            o.x = acc[i][0] * dv;
            o.y = acc[i][1] * dv;
            o.z = acc[i][2] * dv;
            o.w = acc[i][3] * dv;
            ((float4*)(g_tmp + (size_t)row * DD))[lane] = o;
        }
    }
}

// ---------------- per-node gather accumulate ----------------------------------
// out[i] = b + dinv[i]*(tmp[i] + sum_{e in CSR[i]} tmp[src_e]) (+ res[i])
__global__ void __launch_bounds__(256) k_accum(float* __restrict__ out,
                        const float* __restrict__ b,
                        const float* __restrict__ res) {
    int node = (blockIdx.x * blockDim.x + threadIdx.x) >> 5;
    int lane = threadIdx.x & 31;
    if (node >= NN) return;

    const float4* T = (const float4*)g_tmp;
    int s0 = g_start[node];
    int cnt = g_cnt[node];

    float4 a0 = T[(size_t)node * 32 + lane];           // self loop term
    float4 a1 = make_float4(0.f, 0.f, 0.f, 0.f);
    float4 a2 = make_float4(0.f, 0.f, 0.f, 0.f);
    float4 a3 = make_float4(0.f, 0.f, 0.f, 0.f);

    int e = 0;
    for (; e + 4 <= cnt; e += 4) {
        int i0 = g_esrc[s0 + e + 0];
        int i1 = g_esrc[s0 + e + 1];
        int i2 = g_esrc[s0 + e + 2];
        int i3 = g_esrc[s0 + e + 3];
        float4 v0 = T[(size_t)i0 * 32 + lane];
        float4 v1 = T[(size_t)i1 * 32 + lane];
        float4 v2 = T[(size_t)i2 * 32 + lane];
        float4 v3 = T[(size_t)i3 * 32 + lane];
        a0.x += v0.x; a0.y += v0.y; a0.z += v0.z; a0.w += v0.w;
        a1.x += v1.x; a1.y += v1.y; a1.z += v1.z; a1.w += v1.w;
        a2.x += v2.x; a2.y += v2.y; a2.z += v2.z; a2.w += v2.w;
        a3.x += v3.x; a3.y += v3.y; a3.z += v3.z; a3.w += v3.w;
    }
    for (; e < cnt; e++) {
        int i0 = g_esrc[s0 + e];
        float4 v0 = T[(size_t)i0 * 32 + lane];
        a0.x += v0.x; a0.y += v0.y; a0.z += v0.z; a0.w += v0.w;
    }
    a0.x += a1.x + a2.x + a3.x;
    a0.y += a1.y + a2.y + a3.y;
    a0.z += a1.z + a2.z + a3.z;
    a0.w += a1.w + a2.w + a3.w;

    float dv = g_dinv[node];
    float4 bb = ((const float4*)b)[lane];
    float4 o;
    o.x = fmaf(dv, a0.x, bb.x);
    o.y = fmaf(dv, a0.y, bb.y);
    o.z = fmaf(dv, a0.z, bb.z);
    o.w = fmaf(dv, a0.w, bb.w);
    if (res) {
        float4 r = ((const float4*)(res))[(size_t)node * 32 + lane];
        o.x += r.x; o.y += r.y; o.z += r.z; o.w += r.w;
    }
    ((float4*)out)[(size_t)node * 32 + lane] = o;
}

// ---------------- launch ------------------------------------------------------
extern "C" void kernel_launch(void* const* d_in, const int* in_sizes, int n_in,
                              void* d_out, int out_size) {
    const float* x   = (const float*)d_in[0];
    const int*   ei  = (const int*)d_in[1];
    const int*   src = ei;
    const int*   dst = ei + EE;
    const float* lng0 = (const float*)d_in[2];
    const float* lnb0 = (const float*)d_in[3];
    const float* W0   = (const float*)d_in[4];
    const float* b0   = (const float*)d_in[5];
    const float* lng1 = (const float*)d_in[6];
    const float* lnb1 = (const float*)d_in[7];
    const float* W1   = (const float*)d_in[8];
    const float* b1   = (const float*)d_in[9];
    const float* lng2 = (const float*)d_in[10];
    const float* lnb2 = (const float*)d_in[11];
    const float* W2   = (const float*)d_in[12];
    const float* b2   = (const float*)d_in[13];
    float* out = (float*)d_out;

    float* d_x1;  cudaGetSymbolAddress((void**)&d_x1,  g_x1);
    float* d_h2;  cudaGetSymbolAddress((void**)&d_h2,  g_h2);

    // ---- CSR build + dinv ----
    k_zero<<<(NN + 255) / 256, 256>>>();
    k_hist<<<(EE + 255) / 256, 256>>>(dst);
    k_dinv_k<<<(NN + 255) / 256, 256>>>();
    k_scan_a<<<SNB, SCH>>>();
    k_scan_b<<<1, 32>>>();
    k_scan_c<<<SNB, SCH>>>();
    k_bucket<<<(EE + 255) / 256, 256>>>(src, dst);

    const int gemm_blocks = (NN + TR - 1) / TR;
    const int acc_blocks = (NN * 32 + 255) / 256;   // warp per node

    // layer 0: x -> g_x1 (residual = x)
    k_ln_gemm<<<gemm_blocks, 256>>>(x, lng0, lnb0, W0);
    k_accum<<<acc_blocks, 256>>>(d_x1, b0, x);

    // layer 1: g_x1 -> g_h2 (no residual)
    k_ln_gemm<<<gemm_blocks, 256>>>(d_x1, lng1, lnb1, W1);
    k_accum<<<acc_blocks, 256>>>(d_h2, b1, nullptr);

    // layer 2: g_h2 -> out (residual = g_x1)
    k_ln_gemm<<<gemm_blocks, 256>>>(d_h2, lng2, lnb2, W2);
    k_accum<<<acc_blocks, 256>>>(out, b2, d_x1);
}